// round 9
// baseline (speedup 1.0000x reference)
#include <cuda_runtime.h>
#include <cuda_fp16.h>
#include <cstdint>
#include <cstddef>

// Problem dims
#define NB 32
#define NS 2048
#define NH 1024
#define NE 2048              // 2*H
#define NR (NB*NS)           // 65536 rows

// ---------------- device scratch (static, no runtime allocs) ----------------
__device__ __half g_enc_h[(size_t)NR * NE]; // 268 MB: enc converted to fp16
__device__ __half g_Wk_h[NH * NE];          // 4 MB: Wk fp16 (K-major [h][e])
__device__ float  g_query[NB * NH];         // query[b][h]
__device__ float  g_spart[4 * NR];          // partial scores per n-block (4 blocks of 256)
__device__ float  g_alphas[NR];             // softmax result
__device__ float  g_cpart[8 * NB * NE];     // context partials (s-split by 8)

// ---------------- helpers (baseline PTX only: sm_80-era instructions) -------
__device__ __forceinline__ uint32_t smem_u32(const void* p) {
    uint32_t a;
    asm("{ .reg .u64 t; cvta.to.shared.u64 t, %1; cvt.u32.u64 %0, t; }" : "=r"(a) : "l"(p));
    return a;
}
__device__ __forceinline__ void cp16(uint32_t s, const void* g) {
    asm volatile("cp.async.cg.shared.global [%0], [%1], 16;" :: "r"(s), "l"(g));
}
#define CP_COMMIT() asm volatile("cp.async.commit_group;" ::: "memory")
#define CP_WAIT(n)  asm volatile("cp.async.wait_group %0;" :: "n"(n) : "memory")

__device__ __forceinline__ void ldsm4(uint32_t* r, uint32_t addr) {
    asm volatile("ldmatrix.sync.aligned.m8n8.x4.shared.b16 {%0,%1,%2,%3}, [%4];"
        : "=r"(r[0]), "=r"(r[1]), "=r"(r[2]), "=r"(r[3]) : "r"(addr));
}
__device__ __forceinline__ void mma16816(float* c, const uint32_t* a, uint32_t b0, uint32_t b1) {
    asm volatile("mma.sync.aligned.m16n8k16.row.col.f32.f16.f16.f32 "
        "{%0,%1,%2,%3}, {%4,%5,%6,%7}, {%8,%9}, {%0,%1,%2,%3};"
        : "+f"(c[0]), "+f"(c[1]), "+f"(c[2]), "+f"(c[3])
        : "r"(a[0]), "r"(a[1]), "r"(a[2]), "r"(a[3]), "r"(b0), "r"(b1));
}

// SW128 swizzle for 128B rows (conflict-free ldmatrix + cp.async stores)
#define SW128(o) ((o) ^ (((o) >> 3) & 0x70))

// ---------------- smem layout for scores kernel ----------------
// 4 pipeline stages, each: A tile 128x64 fp16 (16 KB) + B tile 256x64 fp16 (32 KB)
#define STAGE_BYTES 49152
#define ST_A(i)     ((i) * STAGE_BYTES)
#define ST_B(i)     ((i) * STAGE_BYTES + 16384)
#define OFF_Q       196608                    // 256 floats
#define OFF_WE      197632                    // 256 floats
#define OFF_RED     198656                    // 16*64 floats = 4 KB
#define SMEM_TOTAL  202752                    // 198 KB

#define KT      64
#define NSTEPS  (NE / KT)                     // 32

// ---------------- prep kernels ----------------
__global__ void enc_convert_kernel(const float* __restrict__ enc) {
    size_t i = (size_t)blockIdx.x * blockDim.x + threadIdx.x;  // over NR*NE/4
    if (i < ((size_t)NR * NE) / 4) {
        float4 f = ((const float4*)enc)[i];
        __half2 a = __floats2half2_rn(f.x, f.y);
        __half2 b = __floats2half2_rn(f.z, f.w);
        ((__half2*)g_enc_h)[2 * i]     = a;
        ((__half2*)g_enc_h)[2 * i + 1] = b;
    }
}
__global__ void wk_convert_kernel(const float* __restrict__ Wk) {
    int i = blockIdx.x * blockDim.x + threadIdx.x;             // over NH*NE/4
    if (i < (NH * NE) / 4) {
        float4 f = ((const float4*)Wk)[i];
        __half2 a = __floats2half2_rn(f.x, f.y);
        __half2 b = __floats2half2_rn(f.z, f.w);
        ((__half2*)g_Wk_h)[2 * i]     = a;
        ((__half2*)g_Wk_h)[2 * i + 1] = b;
    }
}

__global__ void __launch_bounds__(128) query_kernel(const float* __restrict__ dec,
                                                    const float* __restrict__ Wq) {
    __shared__ float ds[NH];
    int b = blockIdx.y, hc = blockIdx.x, tid = threadIdx.x;
    for (int i = tid; i < NH; i += 128) ds[i] = dec[b * NH + i];
    __syncthreads();
    int h = hc * 128 + tid;
    const float* wr = Wq + (size_t)h * NH;
    float a0 = 0, a1 = 0, a2 = 0, a3 = 0;
    for (int e = 0; e < NH; e += 4) {
        a0 += wr[e + 0] * ds[e + 0];
        a1 += wr[e + 1] * ds[e + 1];
        a2 += wr[e + 2] * ds[e + 2];
        a3 += wr[e + 3] * ds[e + 3];
    }
    g_query[b * NH + h] = (a0 + a1) + (a2 + a3);
}

// ---------------- fused scores GEMM (mma.sync fp16, fused tanh/We epilogue) --
// CTA: 128 rows x 256 cols, 512 threads. 16 warps as 2(m) x 8(n); warp tile 64x32.
__device__ __forceinline__ void issue_loads(uint32_t sbase, int stage, int s,
                                            int m0, int nblk, int tid) {
    const __half* ga = g_enc_h + (size_t)m0 * NE + s * KT;
    const __half* gb = g_Wk_h + (size_t)(nblk * 256) * NE + s * KT;
    uint32_t sa = sbase + ST_A(stage);
    uint32_t sbuf = sbase + ST_B(stage);
#pragma unroll
    for (int t = 0; t < 2; ++t) {          // A: 128 rows x 8 chunks of 16B = 1024
        int id = tid + t * 512;
        int r = id >> 3, c = id & 7;
        cp16(sa + SW128(r * 128 + c * 16), ga + (size_t)r * NE + c * 8);
    }
#pragma unroll
    for (int t = 0; t < 4; ++t) {          // B: 256 rows x 8 chunks of 16B = 2048
        int id = tid + t * 512;
        int r = id >> 3, c = id & 7;
        cp16(sbuf + SW128(r * 128 + c * 16), gb + (size_t)r * NE + c * 8);
    }
}

__global__ void __launch_bounds__(512, 1) scores_kernel(const float* __restrict__ We) {
    extern __shared__ char smem[];
    const int tid = threadIdx.x;
    const int wid = tid >> 5;
    const int lid = tid & 31;
    const uint32_t sb = smem_u32(smem);
    const int nblk = blockIdx.x;           // 0..3 (fast dim -> A reuse in L2)
    const int m0 = blockIdx.y * 128;       // row block (within one batch b)
    const int b = m0 >> 11;
    const int wm = wid >> 3;               // 0..1 (64 rows each)
    const int wn = wid & 7;                // 0..7 (32 cols each)

    float* q_s  = (float*)(smem + OFF_Q);
    float* we_s = (float*)(smem + OFF_WE);
    if (tid < 256) {
        int h = nblk * 256 + tid;
        q_s[tid]  = g_query[b * NH + h];
        we_s[tid] = We[h];
    }

    // prologue: prefetch depth 3 into 4 buffers
    issue_loads(sb, 0, 0, m0, nblk, tid); CP_COMMIT();
    issue_loads(sb, 1, 1, m0, nblk, tid); CP_COMMIT();
    issue_loads(sb, 2, 2, m0, nblk, tid); CP_COMMIT();

    float acc[4][4][4];
#pragma unroll
    for (int mi = 0; mi < 4; ++mi)
#pragma unroll
        for (int nj = 0; nj < 4; ++nj)
#pragma unroll
            for (int k = 0; k < 4; ++k) acc[mi][nj][k] = 0.0f;

    const int lrow = lid & 15;
    const int lcol = (lid >> 4) * 16;

    int st_cur = 0;    // buffer holding stage s
    int st_nxt = 3;    // buffer to fill with stage s+3
    for (int s = 0; s < NSTEPS; ++s) {
        // stage s arrival: pending groups before wait = 3 (steady), 2, 1 at tail
        if (s + 2 < NSTEPS)      CP_WAIT(2);
        else if (s + 1 < NSTEPS) CP_WAIT(1);
        else                     CP_WAIT(0);
        __syncthreads();   // single barrier per step: data visibility + write-safety

        // issue AFTER the barrier: everyone has finished reading the buffer
        // being overwritten (stage s+3 reuses the buffer of stage s-1).
        if (s + 3 < NSTEPS) {
            issue_loads(sb, st_nxt, s + 3, m0, nblk, tid); CP_COMMIT();
            if (++st_nxt == 4) st_nxt = 0;
        }

        const uint32_t sa = sb + ST_A(st_cur);
        const uint32_t sbuf = sb + ST_B(st_cur);
        if (++st_cur == 4) st_cur = 0;
#pragma unroll
        for (int kb = 0; kb < 4; ++kb) {
            // B fragments first (8 regs live), then stream A fragments one at a
            // time (4 regs live) -> fits the 128-reg/thread cap without spill.
            uint32_t bf[2][4];
#pragma unroll
            for (int nb2 = 0; nb2 < 2; ++nb2)
                ldsm4(bf[nb2], sbuf + SW128((wn * 32 + nb2 * 16 + lrow) * 128 + kb * 32 + lcol));
#pragma unroll
            for (int mi = 0; mi < 4; ++mi) {
                uint32_t af[4];
                ldsm4(af, sa + SW128((wm * 64 + mi * 16 + lrow) * 128 + kb * 32 + lcol));
#pragma unroll
                for (int nj = 0; nj < 4; ++nj)
                    mma16816(acc[mi][nj], af, bf[nj >> 1][nj & 1], bf[nj >> 1][(nj & 1) + 2]);
            }
        }
    }
    __syncthreads();   // order epilogue smem use after mainloop

    // ---- fused epilogue: tanh(d + q) * we, reduce over 256 cols ----
    float rl[4] = {0, 0, 0, 0}, rh[4] = {0, 0, 0, 0};
#pragma unroll
    for (int mi = 0; mi < 4; ++mi)
#pragma unroll
        for (int nj = 0; nj < 4; ++nj) {
            int col = wn * 32 + nj * 8 + 2 * (lid & 3);
            float q0 = q_s[col], q1 = q_s[col + 1];
            float w0 = we_s[col], w1 = we_s[col + 1];
            rl[mi] += tanhf(acc[mi][nj][0] + q0) * w0 + tanhf(acc[mi][nj][1] + q1) * w1;
            rh[mi] += tanhf(acc[mi][nj][2] + q0) * w0 + tanhf(acc[mi][nj][3] + q1) * w1;
        }
    // quad reduce (lanes 4r..4r+3 share row r)
#pragma unroll
    for (int mi = 0; mi < 4; ++mi) {
        rl[mi] += __shfl_xor_sync(0xFFFFFFFF, rl[mi], 1);
        rl[mi] += __shfl_xor_sync(0xFFFFFFFF, rl[mi], 2);
        rh[mi] += __shfl_xor_sync(0xFFFFFFFF, rh[mi], 1);
        rh[mi] += __shfl_xor_sync(0xFFFFFFFF, rh[mi], 2);
    }
    float* red = (float*)(smem + OFF_RED);   // [16 warps][64 rows]
    if ((lid & 3) == 0) {
        int r = lid >> 2;                    // 0..7
#pragma unroll
        for (int mi = 0; mi < 4; ++mi) {
            red[wid * 64 + mi * 16 + r]     = rl[mi];
            red[wid * 64 + mi * 16 + 8 + r] = rh[mi];
        }
    }
    __syncthreads();
    if (tid < 128) {                         // row = wm*64 + rr  == tid
        int wmv = tid >> 6, rr = tid & 63;
        float sum = 0.0f;
#pragma unroll
        for (int k = 0; k < 8; ++k) sum += red[(wmv * 8 + k) * 64 + rr];
        g_spart[nblk * NR + m0 + tid] = sum;
    }
}

// ---------------- softmax ----------------
__global__ void __launch_bounds__(256) softmax_kernel() {
    __shared__ float sc[NS];
    __shared__ float red[256];
    int b = blockIdx.x, tid = threadIdx.x;
    float mx = -1e30f;
    for (int s = tid; s < NS; s += 256) {
        float v = g_spart[b * NS + s] + g_spart[NR + b * NS + s]
                + g_spart[2 * NR + b * NS + s] + g_spart[3 * NR + b * NS + s];
        sc[s] = v;
        mx = fmaxf(mx, v);
    }
    red[tid] = mx; __syncthreads();
    for (int o = 128; o; o >>= 1) { if (tid < o) red[tid] = fmaxf(red[tid], red[tid + o]); __syncthreads(); }
    mx = red[0]; __syncthreads();
    float sm = 0.0f;
    for (int s = tid; s < NS; s += 256) {
        float e = expf(sc[s] - mx);
        sc[s] = e; sm += e;
    }
    red[tid] = sm; __syncthreads();
    for (int o = 128; o; o >>= 1) { if (tid < o) red[tid] += red[tid + o]; __syncthreads(); }
    float inv = 1.0f / red[0];
    for (int s = tid; s < NS; s += 256) g_alphas[b * NS + s] = sc[s] * inv;
}

// ---------------- context = alphas @ enc (fp16 enc reads: half the DRAM) ----
__global__ void __launch_bounds__(256) ctx_part_kernel() {
    __shared__ float al[256];
    int b = blockIdx.z, jc = blockIdx.x, sc = blockIdx.y, tid = threadIdx.x;
    al[tid] = g_alphas[b * NS + sc * 256 + tid];
    __syncthreads();
    int j = jc * 256 + tid;
    const __half* ep = g_enc_h + ((size_t)b * NS + sc * 256) * NE + j;
    float acc = 0.0f;
#pragma unroll 8
    for (int s = 0; s < 256; ++s) acc += al[s] * __half2float(ep[(size_t)s * NE]);
    g_cpart[(size_t)sc * (NB * NE) + b * NE + j] = acc;
}

__global__ void __launch_bounds__(256) ctx_reduce_kernel(float* __restrict__ out) {
    int i = blockIdx.x * 256 + threadIdx.x;   // 0..65535
    float a = 0.0f;
#pragma unroll
    for (int sc = 0; sc < 8; ++sc) a += g_cpart[sc * (NB * NE) + i];
    out[i] = a;
}

// ---------------- launch ----------------
extern "C" void kernel_launch(void* const* d_in, const int* in_sizes, int n_in,
                              void* d_out, int out_size) {
    const float* enc = (const float*)d_in[0];
    const float* dec = (const float*)d_in[1];
    const float* Wq  = (const float*)d_in[2];
    const float* Wk  = (const float*)d_in[3];
    const float* We  = (const float*)d_in[4];
    float* out = (float*)d_out;

    cudaFuncSetAttribute(scores_kernel, cudaFuncAttributeMaxDynamicSharedMemorySize, SMEM_TOTAL);

    enc_convert_kernel<<<131072, 256>>>(enc);
    wk_convert_kernel<<<2048, 256>>>(Wk);
    query_kernel<<<dim3(8, 32), 128>>>(dec, Wq);
    scores_kernel<<<dim3(4, 512), 512, SMEM_TOTAL>>>(We);
    softmax_kernel<<<32, 256>>>();
    ctx_part_kernel<<<dim3(8, 8, 32), 256>>>();
    ctx_reduce_kernel<<<256, 256>>>(out);
}

// round 11
// speedup vs baseline: 1.0400x; 1.0400x over previous
#include <cuda_runtime.h>
#include <cuda_fp16.h>
#include <cstdint>
#include <cstddef>

// Problem dims
#define NB 32
#define NS 2048
#define NH 1024
#define NE 2048              // 2*H
#define NR (NB*NS)           // 65536 rows

// ---------------- device scratch (static, no runtime allocs) ----------------
__device__ __half g_enc_h[(size_t)NR * NE]; // 268 MB: enc converted to fp16
__device__ __half g_Wk_h[NH * NE];          // 4 MB: Wk fp16 (K-major [h][e])
__device__ float  g_query[NB * NH];         // query[b][h]
__device__ float  g_spart[4 * NR];          // partial scores per n-block (4 blocks of 256)
__device__ float  g_alphas[NR];             // softmax result
__device__ float  g_cpart[8 * NB * NE];     // context partials (s-split by 8)

// ---------------- helpers (baseline PTX only: sm_80-era instructions) -------
__device__ __forceinline__ uint32_t smem_u32(const void* p) {
    uint32_t a;
    asm("{ .reg .u64 t; cvta.to.shared.u64 t, %1; cvt.u32.u64 %0, t; }" : "=r"(a) : "l"(p));
    return a;
}
__device__ __forceinline__ void cp16(uint32_t s, const void* g) {
    asm volatile("cp.async.cg.shared.global [%0], [%1], 16;" :: "r"(s), "l"(g));
}
#define CP_COMMIT() asm volatile("cp.async.commit_group;" ::: "memory")
#define CP_WAIT(n)  asm volatile("cp.async.wait_group %0;" :: "n"(n) : "memory")

__device__ __forceinline__ void ldsm4(uint32_t* r, uint32_t addr) {
    asm volatile("ldmatrix.sync.aligned.m8n8.x4.shared.b16 {%0,%1,%2,%3}, [%4];"
        : "=r"(r[0]), "=r"(r[1]), "=r"(r[2]), "=r"(r[3]) : "r"(addr));
}
__device__ __forceinline__ void mma16816(float* c, const uint32_t* a, uint32_t b0, uint32_t b1) {
    asm volatile("mma.sync.aligned.m16n8k16.row.col.f32.f16.f16.f32 "
        "{%0,%1,%2,%3}, {%4,%5,%6,%7}, {%8,%9}, {%0,%1,%2,%3};"
        : "+f"(c[0]), "+f"(c[1]), "+f"(c[2]), "+f"(c[3])
        : "r"(a[0]), "r"(a[1]), "r"(a[2]), "r"(a[3]), "r"(b0), "r"(b1));
}

// SW128 swizzle for 128B rows (conflict-free ldmatrix + cp.async stores)
#define SW128(o) ((o) ^ (((o) >> 3) & 0x70))

// ---------------- smem layout for scores kernel ----------------
// 4 pipeline stages, each: A tile 128x64 fp16 (16 KB) + B tile 256x64 fp16 (32 KB)
#define STAGE_BYTES 49152
#define ST_A(i)     ((i) * STAGE_BYTES)
#define ST_B(i)     ((i) * STAGE_BYTES + 16384)
#define OFF_Q       196608                    // 256 floats
#define OFF_WE      197632                    // 256 floats
#define OFF_RED     198656                    // 8*64 floats = 2 KB
#define SMEM_TOTAL  200704                    // 196 KB

#define KT      64
#define NSTEPS  (NE / KT)                     // 32

// ---------------- prep kernels ----------------
__global__ void enc_convert_kernel(const float* __restrict__ enc) {
    size_t i = (size_t)blockIdx.x * blockDim.x + threadIdx.x;  // over NR*NE/4
    if (i < ((size_t)NR * NE) / 4) {
        float4 f = ((const float4*)enc)[i];
        __half2 a = __floats2half2_rn(f.x, f.y);
        __half2 b = __floats2half2_rn(f.z, f.w);
        ((__half2*)g_enc_h)[2 * i]     = a;
        ((__half2*)g_enc_h)[2 * i + 1] = b;
    }
}
__global__ void wk_convert_kernel(const float* __restrict__ Wk) {
    int i = blockIdx.x * blockDim.x + threadIdx.x;             // over NH*NE/4
    if (i < (NH * NE) / 4) {
        float4 f = ((const float4*)Wk)[i];
        __half2 a = __floats2half2_rn(f.x, f.y);
        __half2 b = __floats2half2_rn(f.z, f.w);
        ((__half2*)g_Wk_h)[2 * i]     = a;
        ((__half2*)g_Wk_h)[2 * i + 1] = b;
    }
}

__global__ void __launch_bounds__(128) query_kernel(const float* __restrict__ dec,
                                                    const float* __restrict__ Wq) {
    __shared__ float ds[NH];
    int b = blockIdx.y, hc = blockIdx.x, tid = threadIdx.x;
    for (int i = tid; i < NH; i += 128) ds[i] = dec[b * NH + i];
    __syncthreads();
    int h = hc * 128 + tid;
    const float* wr = Wq + (size_t)h * NH;
    float a0 = 0, a1 = 0, a2 = 0, a3 = 0;
    for (int e = 0; e < NH; e += 4) {
        a0 += wr[e + 0] * ds[e + 0];
        a1 += wr[e + 1] * ds[e + 1];
        a2 += wr[e + 2] * ds[e + 2];
        a3 += wr[e + 3] * ds[e + 3];
    }
    g_query[b * NH + h] = (a0 + a1) + (a2 + a3);
}

// ---------------- fused scores GEMM (mma.sync fp16, fused tanh/We epilogue) --
// CTA: 128 rows x 256 cols, 256 threads. 8 warps as 2(m) x 4(n); warp tile 64x64.
__global__ void __launch_bounds__(256, 1) scores_kernel(const float* __restrict__ We) {
    extern __shared__ char smem[];
    const int tid = threadIdx.x;
    const int wid = tid >> 5;
    const int lid = tid & 31;
    const uint32_t sb = smem_u32(smem);
    const int nblk = blockIdx.x;           // 0..3 (fast dim -> A reuse in L2)
    const int m0 = blockIdx.y * 128;       // row block (within one batch b)
    const int b = m0 >> 11;
    const int wm = wid >> 2;               // 0..1 (64 rows)
    const int wn = wid & 3;                // 0..3 (64 cols)

    float* q_s  = (float*)(smem + OFF_Q);
    float* we_s = (float*)(smem + OFF_WE);
    {
        int h = nblk * 256 + tid;
        q_s[tid]  = g_query[b * NH + h];
        we_s[tid] = We[h];
    }

    // ---- precompute all addresses ONCE (kills the per-step ALU storm) ----
    // cp.async: A = 128 rows x 8 chunks (1024 slots / 256 thr = 4), B = 2048/256 = 8
    uint32_t soffA[4], soffB[8];
    uint32_t goffA[4], goffB[8];           // element offsets into gmem (32-bit safe)
#pragma unroll
    for (int t = 0; t < 4; ++t) {
        int id = tid + t * 256, r = id >> 3, c = id & 7;
        soffA[t] = SW128(r * 128 + c * 16);
        goffA[t] = r * NE + c * 8;
    }
#pragma unroll
    for (int t = 0; t < 8; ++t) {
        int id = tid + t * 256, r = id >> 3, c = id & 7;
        soffB[t] = SW128(r * 128 + c * 16);
        goffB[t] = r * NE + c * 8;
    }
    const __half* gA = g_enc_h + (size_t)m0 * NE;
    const __half* gB = g_Wk_h + (size_t)(nblk * 256) * NE;

    // ldmatrix: SW128(row*128 + kb*32 + lcol) == SW128(row*128 + lcol) ^ (kb*32)
    const int lrow = lid & 15;
    const int lcol = (lid >> 4) * 16;
    uint32_t aoff[4], boff[4];
#pragma unroll
    for (int i = 0; i < 4; ++i) {
        uint32_t oa = (uint32_t)(wm * 64 + i * 16 + lrow) * 128 + lcol;
        aoff[i] = SW128(oa);
        uint32_t ob = (uint32_t)(wn * 64 + i * 16 + lrow) * 128 + lcol;
        boff[i] = SW128(ob);
    }

    // issue helper: 12 cp.async with precomputed offsets (1 add each)
    auto issue = [&](int stage, int s) {
        const __half* ga = gA + s * KT;
        const __half* gb = gB + s * KT;
        uint32_t sa = sb + ST_A(stage);
        uint32_t sbB = sb + ST_B(stage);
#pragma unroll
        for (int t = 0; t < 4; ++t) cp16(sa + soffA[t], ga + goffA[t]);
#pragma unroll
        for (int t = 0; t < 8; ++t) cp16(sbB + soffB[t], gb + goffB[t]);
        CP_COMMIT();
    };

    // prologue: prefetch depth 3 into 4 buffers
    issue(0, 0); issue(1, 1); issue(2, 2);

    float acc[4][8][4];
#pragma unroll
    for (int mi = 0; mi < 4; ++mi)
#pragma unroll
        for (int nj = 0; nj < 8; ++nj)
#pragma unroll
            for (int k = 0; k < 4; ++k) acc[mi][nj][k] = 0.0f;

    int st_cur = 0, st_nxt = 3;
    for (int s = 0; s < NSTEPS; ++s) {
        if (s + 2 < NSTEPS)      CP_WAIT(2);
        else if (s + 1 < NSTEPS) CP_WAIT(1);
        else                     CP_WAIT(0);
        __syncthreads();   // single barrier: data visibility + write-safety

        if (s + 3 < NSTEPS) {            // buffer (s+3)&3 == (s-1)&3: safe now
            issue(st_nxt, s + 3);
            if (++st_nxt == 4) st_nxt = 0;
        }

        const uint32_t sa = sb + ST_A(st_cur);
        const uint32_t sbB = sb + ST_B(st_cur);
        if (++st_cur == 4) st_cur = 0;
#pragma unroll
        for (int kb = 0; kb < 4; ++kb) {
            const uint32_t kx = kb << 5;
            uint32_t af[4][4], bf[4][4];
#pragma unroll
            for (int mi = 0; mi < 4; ++mi)
                ldsm4(af[mi], sa + (aoff[mi] ^ kx));
#pragma unroll
            for (int nj2 = 0; nj2 < 4; ++nj2)
                ldsm4(bf[nj2], sbB + (boff[nj2] ^ kx));
#pragma unroll
            for (int mi = 0; mi < 4; ++mi)
#pragma unroll
                for (int nj = 0; nj < 8; ++nj)
                    mma16816(acc[mi][nj], af[mi], bf[nj >> 1][nj & 1], bf[nj >> 1][(nj & 1) + 2]);
        }
    }
    __syncthreads();

    // ---- fused epilogue: tanh(d + q) * we, reduce over 256 cols ----
    float rl[4] = {0, 0, 0, 0}, rh[4] = {0, 0, 0, 0};
#pragma unroll
    for (int mi = 0; mi < 4; ++mi)
#pragma unroll
        for (int nj = 0; nj < 8; ++nj) {
            int col = wn * 64 + nj * 8 + 2 * (lid & 3);
            float q0 = q_s[col], q1 = q_s[col + 1];
            float w0 = we_s[col], w1 = we_s[col + 1];
            rl[mi] += tanhf(acc[mi][nj][0] + q0) * w0 + tanhf(acc[mi][nj][1] + q1) * w1;
            rh[mi] += tanhf(acc[mi][nj][2] + q0) * w0 + tanhf(acc[mi][nj][3] + q1) * w1;
        }
    // quad reduce (lanes 4r..4r+3 share row r)
#pragma unroll
    for (int mi = 0; mi < 4; ++mi) {
        rl[mi] += __shfl_xor_sync(0xFFFFFFFF, rl[mi], 1);
        rl[mi] += __shfl_xor_sync(0xFFFFFFFF, rl[mi], 2);
        rh[mi] += __shfl_xor_sync(0xFFFFFFFF, rh[mi], 1);
        rh[mi] += __shfl_xor_sync(0xFFFFFFFF, rh[mi], 2);
    }
    float* red = (float*)(smem + OFF_RED);   // [8 warps][64 rows]
    if ((lid & 3) == 0) {
        int r = lid >> 2;                    // 0..7
#pragma unroll
        for (int mi = 0; mi < 4; ++mi) {
            red[wid * 64 + mi * 16 + r]     = rl[mi];
            red[wid * 64 + mi * 16 + 8 + r] = rh[mi];
        }
    }
    __syncthreads();
    if (tid < 128) {
        int wmv = tid >> 6, rr = tid & 63;
        float sum = red[(wmv * 4 + 0) * 64 + rr] + red[(wmv * 4 + 1) * 64 + rr]
                  + red[(wmv * 4 + 2) * 64 + rr] + red[(wmv * 4 + 3) * 64 + rr];
        g_spart[nblk * NR + m0 + tid] = sum;
    }
}

// ---------------- softmax ----------------
__global__ void __launch_bounds__(256) softmax_kernel() {
    __shared__ float sc[NS];
    __shared__ float red[256];
    int b = blockIdx.x, tid = threadIdx.x;
    float mx = -1e30f;
    for (int s = tid; s < NS; s += 256) {
        float v = g_spart[b * NS + s] + g_spart[NR + b * NS + s]
                + g_spart[2 * NR + b * NS + s] + g_spart[3 * NR + b * NS + s];
        sc[s] = v;
        mx = fmaxf(mx, v);
    }
    red[tid] = mx; __syncthreads();
    for (int o = 128; o; o >>= 1) { if (tid < o) red[tid] = fmaxf(red[tid], red[tid + o]); __syncthreads(); }
    mx = red[0]; __syncthreads();
    float sm = 0.0f;
    for (int s = tid; s < NS; s += 256) {
        float e = expf(sc[s] - mx);
        sc[s] = e; sm += e;
    }
    red[tid] = sm; __syncthreads();
    for (int o = 128; o; o >>= 1) { if (tid < o) red[tid] += red[tid + o]; __syncthreads(); }
    float inv = 1.0f / red[0];
    for (int s = tid; s < NS; s += 256) g_alphas[b * NS + s] = sc[s] * inv;
}

// ---------------- context = alphas @ enc (fp16 enc reads: half the DRAM) ----
__global__ void __launch_bounds__(256) ctx_part_kernel() {
    __shared__ float al[256];
    int b = blockIdx.z, jc = blockIdx.x, sc = blockIdx.y, tid = threadIdx.x;
    al[tid] = g_alphas[b * NS + sc * 256 + tid];
    __syncthreads();
    int j = jc * 256 + tid;
    const __half* ep = g_enc_h + ((size_t)b * NS + sc * 256) * NE + j;
    float acc = 0.0f;
#pragma unroll 8
    for (int s = 0; s < 256; ++s) acc += al[s] * __half2float(ep[(size_t)s * NE]);
    g_cpart[(size_t)sc * (NB * NE) + b * NE + j] = acc;
}

__global__ void __launch_bounds__(256) ctx_reduce_kernel(float* __restrict__ out) {
    int i = blockIdx.x * 256 + threadIdx.x;   // 0..65535
    float a = 0.0f;
#pragma unroll
    for (int sc = 0; sc < 8; ++sc) a += g_cpart[sc * (NB * NE) + i];
    out[i] = a;
}

// ---------------- launch ----------------
extern "C" void kernel_launch(void* const* d_in, const int* in_sizes, int n_in,
                              void* d_out, int out_size) {
    const float* enc = (const float*)d_in[0];
    const float* dec = (const float*)d_in[1];
    const float* Wq  = (const float*)d_in[2];
    const float* Wk  = (const float*)d_in[3];
    const float* We  = (const float*)d_in[4];
    float* out = (float*)d_out;

    cudaFuncSetAttribute(scores_kernel, cudaFuncAttributeMaxDynamicSharedMemorySize, SMEM_TOTAL);

    enc_convert_kernel<<<131072, 256>>>(enc);
    wk_convert_kernel<<<2048, 256>>>(Wk);
    query_kernel<<<dim3(8, 32), 128>>>(dec, Wq);
    scores_kernel<<<dim3(4, 512), 256, SMEM_TOTAL>>>(We);
    softmax_kernel<<<32, 256>>>();
    ctx_part_kernel<<<dim3(8, 8, 32), 256>>>();
    ctx_reduce_kernel<<<256, 256>>>(out);
}

// round 14
// speedup vs baseline: 1.0627x; 1.0218x over previous
#include <cuda_runtime.h>
#include <cuda_fp16.h>
#include <cstdint>
#include <cstddef>

// Problem dims
#define NB 32
#define NS 2048
#define NH 1024
#define NE 2048              // 2*H
#define NR (NB*NS)           // 65536 rows

// ---------------- device scratch (static, no runtime allocs) ----------------
__device__ __half g_enc_h[(size_t)NR * NE]; // 268 MB: enc converted to fp16
__device__ __half g_Wk_h[NH * NE];          // 4 MB: Wk fp16 (K-major [h][e])
__device__ float  g_query[NB * NH];         // query[b][h]
__device__ float  g_spart[4 * NR];          // partial scores per n-block (4 blocks of 256)
__device__ float  g_alphas[NR];             // softmax result
__device__ float  g_cpart[8 * NB * NE];     // context partials (s-split by 8)

// ---------------- helpers (baseline PTX only: sm_80-era instructions) -------
__device__ __forceinline__ uint32_t smem_u32(const void* p) {
    uint32_t a;
    asm("{ .reg .u64 t; cvta.to.shared.u64 t, %1; cvt.u32.u64 %0, t; }" : "=r"(a) : "l"(p));
    return a;
}
__device__ __forceinline__ void cp16(uint32_t s, const void* g) {
    asm volatile("cp.async.cg.shared.global [%0], [%1], 16;" :: "r"(s), "l"(g));
}
#define CP_COMMIT() asm volatile("cp.async.commit_group;" ::: "memory")
#define CP_WAIT(n)  asm volatile("cp.async.wait_group %0;" :: "n"(n) : "memory")

__device__ __forceinline__ void ldsm4(uint32_t* r, uint32_t addr) {
    asm volatile("ldmatrix.sync.aligned.m8n8.x4.shared.b16 {%0,%1,%2,%3}, [%4];"
        : "=r"(r[0]), "=r"(r[1]), "=r"(r[2]), "=r"(r[3]) : "r"(addr));
}
__device__ __forceinline__ void mma16816(float* c, const uint32_t* a, uint32_t b0, uint32_t b1) {
    asm volatile("mma.sync.aligned.m16n8k16.row.col.f32.f16.f16.f32 "
        "{%0,%1,%2,%3}, {%4,%5,%6,%7}, {%8,%9}, {%0,%1,%2,%3};"
        : "+f"(c[0]), "+f"(c[1]), "+f"(c[2]), "+f"(c[3])
        : "r"(a[0]), "r"(a[1]), "r"(a[2]), "r"(a[3]), "r"(b0), "r"(b1));
}

// SW128 swizzle for 128B rows (conflict-free ldmatrix + cp.async stores)
#define SW128(o) ((o) ^ (((o) >> 3) & 0x70))

// ---------------- smem layout for scores kernel ----------------
// 4 pipeline stages, each: A tile 128x64 fp16 (16 KB) + B tile 256x64 fp16 (32 KB)
#define STAGE_BYTES 49152
#define ST_A(i)     ((i) * STAGE_BYTES)
#define ST_B(i)     ((i) * STAGE_BYTES + 16384)
#define OFF_Q       196608                    // 256 floats
#define OFF_WE      197632                    // 256 floats
#define OFF_RED     198656                    // 8*64 floats = 2 KB
#define SMEM_TOTAL  200704                    // 196 KB

#define KT      64
#define NSTEPS  (NE / KT)                     // 32

// ---------------- prep kernels ----------------
__global__ void enc_convert_kernel(const float* __restrict__ enc) {
    size_t i = (size_t)blockIdx.x * blockDim.x + threadIdx.x;  // over NR*NE/4
    if (i < ((size_t)NR * NE) / 4) {
        float4 f = ((const float4*)enc)[i];
        __half2 a = __floats2half2_rn(f.x, f.y);
        __half2 b = __floats2half2_rn(f.z, f.w);
        ((__half2*)g_enc_h)[2 * i]     = a;
        ((__half2*)g_enc_h)[2 * i + 1] = b;
    }
}
__global__ void wk_convert_kernel(const float* __restrict__ Wk) {
    int i = blockIdx.x * blockDim.x + threadIdx.x;             // over NH*NE/4
    if (i < (NH * NE) / 4) {
        float4 f = ((const float4*)Wk)[i];
        __half2 a = __floats2half2_rn(f.x, f.y);
        __half2 b = __floats2half2_rn(f.z, f.w);
        ((__half2*)g_Wk_h)[2 * i]     = a;
        ((__half2*)g_Wk_h)[2 * i + 1] = b;
    }
}

__global__ void __launch_bounds__(128) query_kernel(const float* __restrict__ dec,
                                                    const float* __restrict__ Wq) {
    __shared__ float ds[NH];
    int b = blockIdx.y, hc = blockIdx.x, tid = threadIdx.x;
    for (int i = tid; i < NH; i += 128) ds[i] = dec[b * NH + i];
    __syncthreads();
    int h = hc * 128 + tid;
    const float* wr = Wq + (size_t)h * NH;
    float a0 = 0, a1 = 0, a2 = 0, a3 = 0;
    for (int e = 0; e < NH; e += 4) {
        a0 += wr[e + 0] * ds[e + 0];
        a1 += wr[e + 1] * ds[e + 1];
        a2 += wr[e + 2] * ds[e + 2];
        a3 += wr[e + 3] * ds[e + 3];
    }
    g_query[b * NH + h] = (a0 + a1) + (a2 + a3);
}

// ---------------- fused scores GEMM (mma.sync fp16, fused tanh/We epilogue) --
// CTA: 128 rows x 256 cols, 256 threads. 8 warps as 2(m) x 4(n); warp tile 64x64.
__global__ void __launch_bounds__(256, 1) scores_kernel(const float* __restrict__ We) {
    extern __shared__ char smem[];
    const int tid = threadIdx.x;
    const int wid = tid >> 5;
    const int lid = tid & 31;
    const uint32_t sb = smem_u32(smem);
    const int nblk = blockIdx.x;           // 0..3 (fast dim -> A reuse in L2)
    const int m0 = blockIdx.y * 128;       // row block (within one batch b)
    const int b = m0 >> 11;
    const int wm = wid >> 2;               // 0..1 (64 rows)
    const int wn = wid & 3;                // 0..3 (64 cols)

    float* q_s  = (float*)(smem + OFF_Q);
    float* we_s = (float*)(smem + OFF_WE);
    {
        int h = nblk * 256 + tid;
        q_s[tid]  = g_query[b * NH + h];
        we_s[tid] = We[h];
    }

    // ---- base offsets (all unroll offsets are LINEAR: swizzle xor-term is
    //      invariant in fragment/chunk index; proven bit-disjointness) ----
    // cp.async: chunk t -> +t*4096 smem, +t*65536 gmem halves (32 rows)
    const uint32_t soff0 = SW128((uint32_t)(tid >> 3) * 128 + (tid & 7) * 16);
    const uint32_t goff0 = (uint32_t)(tid >> 3) * NE + (tid & 7) * 8;
    const __half* gA = g_enc_h + (size_t)m0 * NE + goff0;
    const __half* gB = g_Wk_h + (size_t)(nblk * 256) * NE + goff0;

    // ldmatrix: frag i -> +i*2048; kb -> ^ (kb*32)
    const int lrow = lid & 15;
    const int lcol = (lid >> 4) * 16;
    const uint32_t aoff0 = SW128((uint32_t)(wm * 64 + lrow) * 128 + lcol);
    const uint32_t boff0 = SW128((uint32_t)(wn * 64 + lrow) * 128 + lcol);

    // issue helper: 12 cp.async, linear offsets
    auto issue = [&](int stage, int s) {
        const __half* ga = gA + s * KT;
        const __half* gb = gB + s * KT;
        uint32_t sa  = sb + ST_A(stage) + soff0;
        uint32_t sbB = sb + ST_B(stage) + soff0;
#pragma unroll
        for (int t = 0; t < 4; ++t) cp16(sa + t * 4096, ga + t * 65536);
#pragma unroll
        for (int t = 0; t < 8; ++t) cp16(sbB + t * 4096, gb + t * 65536);
        CP_COMMIT();
    };

    // prologue: prefetch depth 3 into 4 buffers
    issue(0, 0); issue(1, 1); issue(2, 2);

    float acc[4][8][4];
#pragma unroll
    for (int mi = 0; mi < 4; ++mi)
#pragma unroll
        for (int nj = 0; nj < 8; ++nj)
#pragma unroll
            for (int k = 0; k < 4; ++k) acc[mi][nj][k] = 0.0f;

    int st_cur = 0, st_nxt = 3;
    for (int s = 0; s < NSTEPS; ++s) {
        if (s + 2 < NSTEPS)      CP_WAIT(2);
        else if (s + 1 < NSTEPS) CP_WAIT(1);
        else                     CP_WAIT(0);
        __syncthreads();   // single barrier: data visibility + write-safety

        if (s + 3 < NSTEPS) {            // buffer (s+3)&3 == (s-1)&3: safe now
            issue(st_nxt, s + 3);
            if (++st_nxt == 4) st_nxt = 0;
        }

        const uint32_t abase = sb + ST_A(st_cur);
        const uint32_t bbase = sb + ST_B(st_cur);
        if (++st_cur == 4) st_cur = 0;

        // ---- software-pipelined fragments: load kb+1 while mma on kb ----
        uint32_t af[2][4][4], bf[2][4][4];
#define LD_FRAGS(buf, kb_) do { \
        const uint32_t kx_ = (uint32_t)(kb_) << 5; \
        const uint32_t ab_ = abase + (aoff0 ^ kx_); \
        const uint32_t bb_ = bbase + (boff0 ^ kx_); \
        ldsm4(af[buf][0], ab_);        ldsm4(af[buf][1], ab_ + 2048); \
        ldsm4(af[buf][2], ab_ + 4096); ldsm4(af[buf][3], ab_ + 6144); \
        ldsm4(bf[buf][0], bb_);        ldsm4(bf[buf][1], bb_ + 2048); \
        ldsm4(bf[buf][2], bb_ + 4096); ldsm4(bf[buf][3], bb_ + 6144); \
    } while (0)

        LD_FRAGS(0, 0);
#pragma unroll
        for (int kb = 0; kb < 4; ++kb) {
            const int cur = kb & 1;
            if (kb < 3) LD_FRAGS(cur ^ 1, kb + 1);
#pragma unroll
            for (int mi = 0; mi < 4; ++mi)
#pragma unroll
                for (int nj = 0; nj < 8; ++nj)
                    mma16816(acc[mi][nj], af[cur][mi],
                             bf[cur][nj >> 1][nj & 1], bf[cur][nj >> 1][(nj & 1) + 2]);
        }
#undef LD_FRAGS
    }
    __syncthreads();

    // ---- fused epilogue: tanh(d + q) * we, reduce over 256 cols ----
    float rl[4] = {0, 0, 0, 0}, rh[4] = {0, 0, 0, 0};
#pragma unroll
    for (int mi = 0; mi < 4; ++mi)
#pragma unroll
        for (int nj = 0; nj < 8; ++nj) {
            int col = wn * 64 + nj * 8 + 2 * (lid & 3);
            float q0 = q_s[col], q1 = q_s[col + 1];
            float w0 = we_s[col], w1 = we_s[col + 1];
            rl[mi] += tanhf(acc[mi][nj][0] + q0) * w0 + tanhf(acc[mi][nj][1] + q1) * w1;
            rh[mi] += tanhf(acc[mi][nj][2] + q0) * w0 + tanhf(acc[mi][nj][3] + q1) * w1;
        }
    // quad reduce (lanes 4r..4r+3 share row r)
#pragma unroll
    for (int mi = 0; mi < 4; ++mi) {
        rl[mi] += __shfl_xor_sync(0xFFFFFFFF, rl[mi], 1);
        rl[mi] += __shfl_xor_sync(0xFFFFFFFF, rl[mi], 2);
        rh[mi] += __shfl_xor_sync(0xFFFFFFFF, rh[mi], 1);
        rh[mi] += __shfl_xor_sync(0xFFFFFFFF, rh[mi], 2);
    }
    float* red = (float*)(smem + OFF_RED);   // [8 warps][64 rows]
    if ((lid & 3) == 0) {
        int r = lid >> 2;                    // 0..7
#pragma unroll
        for (int mi = 0; mi < 4; ++mi) {
            red[wid * 64 + mi * 16 + r]     = rl[mi];
            red[wid * 64 + mi * 16 + 8 + r] = rh[mi];
        }
    }
    __syncthreads();
    if (tid < 128) {
        int wmv = tid >> 6, rr = tid & 63;
        float sum = red[(wmv * 4 + 0) * 64 + rr] + red[(wmv * 4 + 1) * 64 + rr]
                  + red[(wmv * 4 + 2) * 64 + rr] + red[(wmv * 4 + 3) * 64 + rr];
        g_spart[nblk * NR + m0 + tid] = sum;
    }
}

// ---------------- softmax ----------------
__global__ void __launch_bounds__(256) softmax_kernel() {
    __shared__ float sc[NS];
    __shared__ float red[256];
    int b = blockIdx.x, tid = threadIdx.x;
    float mx = -1e30f;
    for (int s = tid; s < NS; s += 256) {
        float v = g_spart[b * NS + s] + g_spart[NR + b * NS + s]
                + g_spart[2 * NR + b * NS + s] + g_spart[3 * NR + b * NS + s];
        sc[s] = v;
        mx = fmaxf(mx, v);
    }
    red[tid] = mx; __syncthreads();
    for (int o = 128; o; o >>= 1) { if (tid < o) red[tid] = fmaxf(red[tid], red[tid + o]); __syncthreads(); }
    mx = red[0]; __syncthreads();
    float sm = 0.0f;
    for (int s = tid; s < NS; s += 256) {
        float e = expf(sc[s] - mx);
        sc[s] = e; sm += e;
    }
    red[tid] = sm; __syncthreads();
    for (int o = 128; o; o >>= 1) { if (tid < o) red[tid] += red[tid + o]; __syncthreads(); }
    float inv = 1.0f / red[0];
    for (int s = tid; s < NS; s += 256) g_alphas[b * NS + s] = sc[s] * inv;
}

// ---------------- context = alphas @ enc (half2-vectorized fp16 reads) ------
// grid (4, 8, 32): each thread produces TWO adjacent output columns via one
// 4-byte half2 load per s-row (half the load-issue count of the scalar form).
__global__ void __launch_bounds__(256) ctx_part_kernel() {
    __shared__ float al[256];
    int b = blockIdx.z, jc = blockIdx.x, sc = blockIdx.y, tid = threadIdx.x;
    al[tid] = g_alphas[b * NS + sc * 256 + tid];
    __syncthreads();
    int h2 = jc * 256 + tid;               // half2 index, 0..1023
    const __half2* ep2 = (const __half2*)(g_enc_h + ((size_t)b * NS + sc * 256) * NE) + h2;
    float acc0 = 0.0f, acc1 = 0.0f;
#pragma unroll 8
    for (int s = 0; s < 256; ++s) {
        float2 v = __half22float2(ep2[(size_t)s * (NE / 2)]);
        float a = al[s];
        acc0 += a * v.x;
        acc1 += a * v.y;
    }
    float* outp = &g_cpart[(size_t)sc * (NB * NE) + b * NE + 2 * h2];
    outp[0] = acc0;
    outp[1] = acc1;
}

__global__ void __launch_bounds__(256) ctx_reduce_kernel(float* __restrict__ out) {
    int i = blockIdx.x * 256 + threadIdx.x;   // 0..65535
    float a = 0.0f;
#pragma unroll
    for (int sc = 0; sc < 8; ++sc) a += g_cpart[sc * (NB * NE) + i];
    out[i] = a;
}

// ---------------- launch ----------------
extern "C" void kernel_launch(void* const* d_in, const int* in_sizes, int n_in,
                              void* d_out, int out_size) {
    const float* enc = (const float*)d_in[0];
    const float* dec = (const float*)d_in[1];
    const float* Wq  = (const float*)d_in[2];
    const float* Wk  = (const float*)d_in[3];
    const float* We  = (const float*)d_in[4];
    float* out = (float*)d_out;

    cudaFuncSetAttribute(scores_kernel, cudaFuncAttributeMaxDynamicSharedMemorySize, SMEM_TOTAL);

    enc_convert_kernel<<<131072, 256>>>(enc);
    wk_convert_kernel<<<2048, 256>>>(Wk);
    query_kernel<<<dim3(8, 32), 128>>>(dec, Wq);
    scores_kernel<<<dim3(4, 512), 256, SMEM_TOTAL>>>(We);
    softmax_kernel<<<32, 256>>>();
    ctx_part_kernel<<<dim3(4, 8, 32), 256>>>();
    ctx_reduce_kernel<<<256, 256>>>(out);
}